// round 9
// baseline (speedup 1.0000x reference)
#include <cuda_runtime.h>
#include <cstdint>

// ---------------- dp2a: d = c + a.s16[0]*b.s8[lo0] + a.s16[1]*b.s8[lo1] ----------------
__device__ __forceinline__ int dp2a_lo(int a_pair, int b_bytes, int c) {
    int d;
    asm("dp2a.lo.s32.s32 %0, %1, %2, %3;" : "=r"(d) : "r"(a_pair), "r"(b_bytes), "r"(c));
    return d;
}
__device__ __forceinline__ int dp2a_hi(int a_pair, int b_bytes, int c) {
    int d;
    asm("dp2a.hi.s32.s32 %0, %1, %2, %3;" : "=r"(d) : "r"(a_pair), "r"(b_bytes), "r"(c));
    return d;
}
// pack two s32 (|v|<=32767) into s16x2 word
__device__ __forceinline__ uint32_t pk16(int q0, int q1) {
    return (uint32_t)(q0 & 0xFFFF) | ((uint32_t)q1 << 16);
}

// ---------------- prepped weights: device globals -> constant mirrors ----------------
// int8 weights packed 4/word, K-major per output channel; (ws, bias) float2 per channel.
__device__ __align__(16) int    g_w1i[64 * 4];    // L1: 64 ch x 16 k
__device__ __align__(16) int    g_w2i[32 * 16];   // L2: 32 ch x 64 k
__device__ __align__(16) int    g_w3i[32 * 8];    // L3: 32 ch x 32 k
__device__ __align__(16) int    g_w4i[8 * 8];     // L4: 5 ch x 32 k (rows 5-7 zero)
__device__ __align__(16) float2 g_s1[64];
__device__ __align__(16) float2 g_s2[32];
__device__ __align__(16) float2 g_s3[32];
__device__ __align__(16) float2 g_s4[8];

__constant__ __align__(16) int    c_w1i[64 * 4];
__constant__ __align__(16) int    c_w2i[32 * 16];
__constant__ __align__(16) int    c_w3i[32 * 8];
__constant__ __align__(16) int    c_w4i[8 * 8];
__constant__ __align__(16) float2 c_s1[64];
__constant__ __align__(16) float2 c_s2[32];
__constant__ __align__(16) float2 c_s3[32];
__constant__ __align__(16) float2 c_s4[8];

// ---------------- HAWQ weight quantization (exact int8) ----------------
// ws = max|W|/127 ; w_int = clip(rint(W/ws), -127, 127). rintf = half-even = jnp.round.
__device__ __forceinline__ int qw(float w, float ws) {
    float q = rintf(__fdiv_rn(w, ws));
    q = fminf(fmaxf(q, -127.0f), 127.0f);
    return (int)q;
}

__global__ void prep_kernel(const float* __restrict__ W1, const float* __restrict__ b1,
                            const float* __restrict__ W2, const float* __restrict__ b2,
                            const float* __restrict__ W3, const float* __restrict__ b3,
                            const float* __restrict__ W4, const float* __restrict__ b4)
{
    int t = threadIdx.x;

    if (t < 64) {                       // L1 channel t, K=16
        float m = 0.0f;
        #pragma unroll
        for (int i = 0; i < 16; i++) m = fmaxf(m, fabsf(W1[t * 16 + i]));
        float ws = __fdiv_rn(m, 127.0f);
        #pragma unroll
        for (int w = 0; w < 4; w++) {
            int v = 0;
            #pragma unroll
            for (int bnum = 0; bnum < 4; bnum++)
                v |= (qw(W1[t * 16 + 4 * w + bnum], ws) & 0xFF) << (8 * bnum);
            g_w1i[t * 4 + w] = v;
        }
        g_s1[t] = make_float2(ws, b1[t]);
    } else if (t < 96) {                // L2 channel t-64, K=64
        int k = t - 64;
        float m = 0.0f;
        #pragma unroll
        for (int j = 0; j < 64; j++) m = fmaxf(m, fabsf(W2[k * 64 + j]));
        float ws = __fdiv_rn(m, 127.0f);
        #pragma unroll
        for (int w = 0; w < 16; w++) {
            int v = 0;
            #pragma unroll
            for (int bnum = 0; bnum < 4; bnum++)
                v |= (qw(W2[k * 64 + 4 * w + bnum], ws) & 0xFF) << (8 * bnum);
            g_w2i[k * 16 + w] = v;
        }
        g_s2[k] = make_float2(ws, b2[k]);
    } else if (t < 128) {               // L3 channel t-96, K=32
        int k = t - 96;
        float m = 0.0f;
        #pragma unroll
        for (int j = 0; j < 32; j++) m = fmaxf(m, fabsf(W3[k * 32 + j]));
        float ws = __fdiv_rn(m, 127.0f);
        #pragma unroll
        for (int w = 0; w < 8; w++) {
            int v = 0;
            #pragma unroll
            for (int bnum = 0; bnum < 4; bnum++)
                v |= (qw(W3[k * 32 + 4 * w + bnum], ws) & 0xFF) << (8 * bnum);
            g_w3i[k * 8 + w] = v;
        }
        g_s3[k] = make_float2(ws, b3[k]);
    }

    if (t < 5) {                        // L4 channel t, K=32
        float m = 0.0f;
        #pragma unroll
        for (int j = 0; j < 32; j++) m = fmaxf(m, fabsf(W4[t * 32 + j]));
        float ws = __fdiv_rn(m, 127.0f);
        #pragma unroll
        for (int w = 0; w < 8; w++) {
            int v = 0;
            #pragma unroll
            for (int bnum = 0; bnum < 4; bnum++)
                v |= (qw(W4[t * 32 + 4 * w + bnum], ws) & 0xFF) << (8 * bnum);
            g_w4i[t * 8 + w] = v;
        }
        g_s4[t] = make_float2(ws, b4[t]);
    } else if (t < 8) {
        #pragma unroll
        for (int w = 0; w < 8; w++) g_w4i[t * 8 + w] = 0;
        g_s4[t] = make_float2(0.0f, 0.0f);
    }
}

// ---------------- fused MLP: 2 rows/thread, exact int16xint8 GEMMs via dp2a ----------------
__global__ __launch_bounds__(128)
void mlp_kernel(const float* __restrict__ x, float* __restrict__ out, int B)
{
    long tid = (long)blockIdx.x * 128 + threadIdx.x;
    long r0 = tid * 2;
    if (r0 >= B) return;
    int nr = (int)((B - r0 >= 2) ? 2 : (B - r0));

    // ---- input: load, per-row int16 quantize, pack ----
    uint32_t xp[2][8];
    float sx[2];
    #pragma unroll
    for (int r = 0; r < 2; r++) {
        long rowc = (r < nr) ? (r0 + r) : (r0);
        const float4* xr = (const float4*)(x + (size_t)rowc * 16);
        float4 v0 = xr[0], v1 = xr[1], v2 = xr[2], v3 = xr[3];
        float xs[16] = {v0.x, v0.y, v0.z, v0.w, v1.x, v1.y, v1.z, v1.w,
                        v2.x, v2.y, v2.z, v2.w, v3.x, v3.y, v3.z, v3.w};
        float m = 0.0f;
        #pragma unroll
        for (int i = 0; i < 16; i++) m = fmaxf(m, fabsf(xs[i]));
        float inv = (m > 0.0f) ? __fdiv_rn(32767.0f, m) : 0.0f;
        sx[r] = m * (1.0f / 32767.0f);
        #pragma unroll
        for (int p = 0; p < 8; p++)
            xp[r][p] = pk16(__float2int_rn(xs[2 * p] * inv),
                            __float2int_rn(xs[2 * p + 1] * inv));
    }

    // ---- L1: 16 -> 64 (exact int GEMM, fp32 dequant + relu) ----
    float h1[2][64];
    #pragma unroll
    for (int j0 = 0; j0 < 64; j0 += 4) {
        int acc[2][4];
        #pragma unroll
        for (int u = 0; u < 4; u++) { acc[0][u] = 0; acc[1][u] = 0; }
        #pragma unroll
        for (int w = 0; w < 4; w++) {
            #pragma unroll
            for (int u = 0; u < 4; u++) {
                int wv = c_w1i[(j0 + u) * 4 + w];
                acc[0][u] = dp2a_lo(xp[0][2 * w], wv, acc[0][u]);
                acc[0][u] = dp2a_hi(xp[0][2 * w + 1], wv, acc[0][u]);
                acc[1][u] = dp2a_lo(xp[1][2 * w], wv, acc[1][u]);
                acc[1][u] = dp2a_hi(xp[1][2 * w + 1], wv, acc[1][u]);
            }
        }
        #pragma unroll
        for (int u = 0; u < 4; u++) {
            float2 s = c_s1[j0 + u];
            h1[0][j0 + u] = fmaxf(fmaf((float)acc[0][u] * s.x, sx[0], s.y), 0.0f);
            h1[1][j0 + u] = fmaxf(fmaf((float)acc[1][u] * s.x, sx[1], s.y), 0.0f);
        }
    }

    // ---- requant h1 -> int16 (per-row scale) ----
    uint32_t a1[2][32];
    float s1[2];
    #pragma unroll
    for (int r = 0; r < 2; r++) {
        float m = 0.0f;
        #pragma unroll
        for (int j = 0; j < 64; j++) m = fmaxf(m, h1[r][j]);
        float inv = (m > 0.0f) ? __fdiv_rn(32767.0f, m) : 0.0f;
        s1[r] = m * (1.0f / 32767.0f);
        #pragma unroll
        for (int p = 0; p < 32; p++)
            a1[r][p] = pk16(__float2int_rn(h1[r][2 * p] * inv),
                            __float2int_rn(h1[r][2 * p + 1] * inv));
    }

    // ---- L2: 64 -> 32 ----
    float h2[2][32];
    #pragma unroll
    for (int j0 = 0; j0 < 32; j0 += 4) {
        int acc[2][4];
        #pragma unroll
        for (int u = 0; u < 4; u++) { acc[0][u] = 0; acc[1][u] = 0; }
        #pragma unroll
        for (int w = 0; w < 16; w++) {
            #pragma unroll
            for (int u = 0; u < 4; u++) {
                int wv = c_w2i[(j0 + u) * 16 + w];
                acc[0][u] = dp2a_lo(a1[0][2 * w], wv, acc[0][u]);
                acc[0][u] = dp2a_hi(a1[0][2 * w + 1], wv, acc[0][u]);
                acc[1][u] = dp2a_lo(a1[1][2 * w], wv, acc[1][u]);
                acc[1][u] = dp2a_hi(a1[1][2 * w + 1], wv, acc[1][u]);
            }
        }
        #pragma unroll
        for (int u = 0; u < 4; u++) {
            float2 s = c_s2[j0 + u];
            h2[0][j0 + u] = fmaxf(fmaf((float)acc[0][u] * s.x, s1[0], s.y), 0.0f);
            h2[1][j0 + u] = fmaxf(fmaf((float)acc[1][u] * s.x, s1[1], s.y), 0.0f);
        }
    }

    // ---- requant h2 ----
    uint32_t a2[2][16];
    float s2[2];
    #pragma unroll
    for (int r = 0; r < 2; r++) {
        float m = 0.0f;
        #pragma unroll
        for (int j = 0; j < 32; j++) m = fmaxf(m, h2[r][j]);
        float inv = (m > 0.0f) ? __fdiv_rn(32767.0f, m) : 0.0f;
        s2[r] = m * (1.0f / 32767.0f);
        #pragma unroll
        for (int p = 0; p < 16; p++)
            a2[r][p] = pk16(__float2int_rn(h2[r][2 * p] * inv),
                            __float2int_rn(h2[r][2 * p + 1] * inv));
    }

    // ---- L3: 32 -> 32 ----
    float h3[2][32];
    #pragma unroll
    for (int j0 = 0; j0 < 32; j0 += 4) {
        int acc[2][4];
        #pragma unroll
        for (int u = 0; u < 4; u++) { acc[0][u] = 0; acc[1][u] = 0; }
        #pragma unroll
        for (int w = 0; w < 8; w++) {
            #pragma unroll
            for (int u = 0; u < 4; u++) {
                int wv = c_w3i[(j0 + u) * 8 + w];
                acc[0][u] = dp2a_lo(a2[0][2 * w], wv, acc[0][u]);
                acc[0][u] = dp2a_hi(a2[0][2 * w + 1], wv, acc[0][u]);
                acc[1][u] = dp2a_lo(a2[1][2 * w], wv, acc[1][u]);
                acc[1][u] = dp2a_hi(a2[1][2 * w + 1], wv, acc[1][u]);
            }
        }
        #pragma unroll
        for (int u = 0; u < 4; u++) {
            float2 s = c_s3[j0 + u];
            h3[0][j0 + u] = fmaxf(fmaf((float)acc[0][u] * s.x, s2[0], s.y), 0.0f);
            h3[1][j0 + u] = fmaxf(fmaf((float)acc[1][u] * s.x, s2[1], s.y), 0.0f);
        }
    }

    // ---- requant h3 ----
    uint32_t a3[2][16];
    float s3[2];
    #pragma unroll
    for (int r = 0; r < 2; r++) {
        float m = 0.0f;
        #pragma unroll
        for (int j = 0; j < 32; j++) m = fmaxf(m, h3[r][j]);
        float inv = (m > 0.0f) ? __fdiv_rn(32767.0f, m) : 0.0f;
        s3[r] = m * (1.0f / 32767.0f);
        #pragma unroll
        for (int p = 0; p < 16; p++)
            a3[r][p] = pk16(__float2int_rn(h3[r][2 * p] * inv),
                            __float2int_rn(h3[r][2 * p + 1] * inv));
    }

    // ---- L4: 32 -> 5, softmax, store ----
    #pragma unroll
    for (int r = 0; r < 2; r++) {
        if (r >= nr) break;
        int acc[5] = {0, 0, 0, 0, 0};
        #pragma unroll
        for (int w = 0; w < 8; w++) {
            #pragma unroll
            for (int mch = 0; mch < 5; mch++) {
                int wv = c_w4i[mch * 8 + w];
                acc[mch] = dp2a_lo(a3[r][2 * w], wv, acc[mch]);
                acc[mch] = dp2a_hi(a3[r][2 * w + 1], wv, acc[mch]);
            }
        }
        float l[5];
        #pragma unroll
        for (int mch = 0; mch < 5; mch++) {
            float2 s = c_s4[mch];
            l[mch] = fmaf((float)acc[mch] * s.x, s3[r], s.y);
        }
        float mx = l[0];
        #pragma unroll
        for (int i = 1; i < 5; i++) mx = fmaxf(mx, l[i]);
        float sum = 0.0f;
        #pragma unroll
        for (int i = 0; i < 5; i++) { l[i] = __expf(l[i] - mx); sum += l[i]; }
        float inv = __fdiv_rn(1.0f, sum);
        float* po = out + (size_t)(r0 + r) * 5;
        #pragma unroll
        for (int i = 0; i < 5; i++) po[i] = l[i] * inv;
    }
}

// ---------------- launch ----------------
extern "C" void kernel_launch(void* const* d_in, const int* in_sizes, int n_in,
                              void* d_out, int out_size)
{
    const float* x  = (const float*)d_in[0];
    const float* W1 = (const float*)d_in[1];
    const float* b1 = (const float*)d_in[2];
    const float* W2 = (const float*)d_in[3];
    const float* b2 = (const float*)d_in[4];
    const float* W3 = (const float*)d_in[5];
    const float* b3 = (const float*)d_in[6];
    const float* W4 = (const float*)d_in[7];
    const float* b4 = (const float*)d_in[8];

    int B = in_sizes[0] / 16;

    prep_kernel<<<1, 128>>>(W1, b1, W2, b2, W3, b3, W4, b4);

    // Mirror packed weights into the constant bank (graph-legal async D2D).
    void *pw1, *pw2, *pw3, *pw4, *ps1, *ps2, *ps3, *ps4;
    cudaGetSymbolAddress(&pw1, g_w1i);
    cudaGetSymbolAddress(&pw2, g_w2i);
    cudaGetSymbolAddress(&pw3, g_w3i);
    cudaGetSymbolAddress(&pw4, g_w4i);
    cudaGetSymbolAddress(&ps1, g_s1);
    cudaGetSymbolAddress(&ps2, g_s2);
    cudaGetSymbolAddress(&ps3, g_s3);
    cudaGetSymbolAddress(&ps4, g_s4);
    cudaMemcpyToSymbolAsync(c_w1i, pw1, sizeof(c_w1i), 0, cudaMemcpyDeviceToDevice, 0);
    cudaMemcpyToSymbolAsync(c_w2i, pw2, sizeof(c_w2i), 0, cudaMemcpyDeviceToDevice, 0);
    cudaMemcpyToSymbolAsync(c_w3i, pw3, sizeof(c_w3i), 0, cudaMemcpyDeviceToDevice, 0);
    cudaMemcpyToSymbolAsync(c_w4i, pw4, sizeof(c_w4i), 0, cudaMemcpyDeviceToDevice, 0);
    cudaMemcpyToSymbolAsync(c_s1, ps1, sizeof(c_s1), 0, cudaMemcpyDeviceToDevice, 0);
    cudaMemcpyToSymbolAsync(c_s2, ps2, sizeof(c_s2), 0, cudaMemcpyDeviceToDevice, 0);
    cudaMemcpyToSymbolAsync(c_s3, ps3, sizeof(c_s3), 0, cudaMemcpyDeviceToDevice, 0);
    cudaMemcpyToSymbolAsync(c_s4, ps4, sizeof(c_s4), 0, cudaMemcpyDeviceToDevice, 0);

    long threads = ((long)B + 1) / 2;
    int blocks = (int)((threads + 127) / 128);
    mlp_kernel<<<blocks, 128>>>(x, (float*)d_out, B);
}

// round 12
// speedup vs baseline: 2.1070x; 2.1070x over previous
#include <cuda_runtime.h>
#include <cuda_bf16.h>
#include <cstdint>

typedef unsigned long long ull;

// ================= fragment tables (device globals, filled by prep) =================
// b-fragment per (kt, nt, lane): two .b32 words, each = one int8-valued weight
// duplicated into both bf16 halves (multiplies the hi and lo A halves).
__device__ __align__(16) ull    g_f1[2 * 8 * 32];   // L1: K=32 (2 kt), N=64 (8 nt)
__device__ __align__(16) ull    g_f2[8 * 4 * 32];   // L2: K=128, N=32
__device__ __align__(16) ull    g_f3[4 * 4 * 32];   // L3: K=64,  N=32
__device__ __align__(16) ull    g_f4[4 * 1 * 32];   // L4: K=64,  N=8 (5 real)
__device__ __align__(16) float2 g_sc1[64];          // (ws, bias) per channel
__device__ __align__(16) float2 g_sc2[32];
__device__ __align__(16) float2 g_sc3[32];
__device__ __align__(16) float2 g_sc4[8];

__device__ __forceinline__ uint32_t dupbf(float w) {
    uint16_t b = __bfloat16_as_ushort(__float2bfloat16(w));   // exact for |int|<=127
    return (uint32_t)b | ((uint32_t)b << 16);
}
// hi/lo double-bf16 split, packed: low16 = bf16(v), high16 = bf16(v - hi)
__device__ __forceinline__ uint32_t splitbf(float v) {
    __nv_bfloat16 h = __float2bfloat16(v);
    float hf = __bfloat162float(h);
    uint16_t hb = __bfloat16_as_ushort(h);
    uint16_t lb = __bfloat16_as_ushort(__float2bfloat16(v - hf));
    return (uint32_t)hb | ((uint32_t)lb << 16);
}

// HAWQ weight quant (exact): ws = max|W|/127 ; w_int = clip(rint(W/ws), -127, 127)
__device__ __forceinline__ float qw(float w, float ws) {
    float q = rintf(__fdiv_rn(w, ws));
    return fminf(fmaxf(q, -127.0f), 127.0f);
}

__global__ void prep_kernel(const float* __restrict__ W1, const float* __restrict__ b1,
                            const float* __restrict__ W2, const float* __restrict__ b2,
                            const float* __restrict__ W3, const float* __restrict__ b3,
                            const float* __restrict__ W4, const float* __restrict__ b4)
{
    __shared__ float sw1[64 * 16];
    __shared__ float sw2[32 * 64];
    __shared__ float sw3[32 * 32];
    __shared__ float sw4[8 * 32];
    int t = threadIdx.x;

    if (t < 64) {
        float m = 0.0f;
        #pragma unroll
        for (int i = 0; i < 16; i++) m = fmaxf(m, fabsf(W1[t * 16 + i]));
        float ws = __fdiv_rn(m, 127.0f);
        #pragma unroll
        for (int i = 0; i < 16; i++) sw1[t * 16 + i] = qw(W1[t * 16 + i], ws);
        g_sc1[t] = make_float2(ws, b1[t]);
    } else if (t < 96) {
        int k = t - 64;
        float m = 0.0f;
        #pragma unroll
        for (int j = 0; j < 64; j++) m = fmaxf(m, fabsf(W2[k * 64 + j]));
        float ws = __fdiv_rn(m, 127.0f);
        #pragma unroll
        for (int j = 0; j < 64; j++) sw2[k * 64 + j] = qw(W2[k * 64 + j], ws);
        g_sc2[k] = make_float2(ws, b2[k]);
    } else {
        int k = t - 96;
        float m = 0.0f;
        #pragma unroll
        for (int j = 0; j < 32; j++) m = fmaxf(m, fabsf(W3[k * 32 + j]));
        float ws = __fdiv_rn(m, 127.0f);
        #pragma unroll
        for (int j = 0; j < 32; j++) sw3[k * 32 + j] = qw(W3[k * 32 + j], ws);
        g_sc3[k] = make_float2(ws, b3[k]);
    }
    if (t < 5) {
        float m = 0.0f;
        #pragma unroll
        for (int j = 0; j < 32; j++) m = fmaxf(m, fabsf(W4[t * 32 + j]));
        float ws = __fdiv_rn(m, 127.0f);
        #pragma unroll
        for (int j = 0; j < 32; j++) sw4[t * 32 + j] = qw(W4[t * 32 + j], ws);
        g_sc4[t] = make_float2(ws, b4[t]);
    } else if (t < 8) {
        #pragma unroll
        for (int j = 0; j < 32; j++) sw4[t * 32 + j] = 0.0f;
        g_sc4[t] = make_float2(0.0f, 0.0f);
    }
    __syncthreads();

    // Fragment tables. index i = ((kt*NT)+nt)*32 + lane ; n = 8*nt+g ; c0 = 8*kt+tg.
    for (int i = t; i < 512; i += 128) {       // L1: KT=2, NT=8, Kch=16
        int kt = i >> 8, rem = i & 255, nt = rem >> 5, lane = rem & 31;
        int g = lane >> 2, tg = lane & 3, n = 8 * nt + g, c0 = 8 * kt + tg;
        g_f1[i] = (ull)dupbf(sw1[n * 16 + c0]) | ((ull)dupbf(sw1[n * 16 + c0 + 4]) << 32);
    }
    for (int i = t; i < 1024; i += 128) {      // L2: KT=8, NT=4, Kch=64
        int kt = i >> 7, rem = i & 127, nt = rem >> 5, lane = rem & 31;
        int g = lane >> 2, tg = lane & 3, n = 8 * nt + g, c0 = 8 * kt + tg;
        g_f2[i] = (ull)dupbf(sw2[n * 64 + c0]) | ((ull)dupbf(sw2[n * 64 + c0 + 4]) << 32);
    }
    for (int i = t; i < 512; i += 128) {       // L3: KT=4, NT=4, Kch=32
        int kt = i >> 7, rem = i & 127, nt = rem >> 5, lane = rem & 31;
        int g = lane >> 2, tg = lane & 3, n = 8 * nt + g, c0 = 8 * kt + tg;
        g_f3[i] = (ull)dupbf(sw3[n * 32 + c0]) | ((ull)dupbf(sw3[n * 32 + c0 + 4]) << 32);
    }
    if (t < 128) {                              // L4: KT=4, NT=1, Kch=32
        int i = t;
        int kt = i >> 5, lane = i & 31;
        int g = lane >> 2, tg = lane & 3, n = g, c0 = 8 * kt + tg;
        g_f4[i] = (ull)dupbf(sw4[n * 32 + c0]) | ((ull)dupbf(sw4[n * 32 + c0 + 4]) << 32);
    }
}

// ================= mma.sync m16n8k16 bf16 (sm_80+ PTX; runs on tensor pipe) =========
__device__ __forceinline__ void mma16816(float* c, uint32_t a0, uint32_t a1,
                                         uint32_t a2, uint32_t a3,
                                         uint32_t b0, uint32_t b1) {
    asm volatile(
        "mma.sync.aligned.m16n8k16.row.col.f32.bf16.bf16.f32 "
        "{%0,%1,%2,%3}, {%4,%5,%6,%7}, {%8,%9}, {%0,%1,%2,%3};"
        : "+f"(c[0]), "+f"(c[1]), "+f"(c[2]), "+f"(c[3])
        : "r"(a0), "r"(a1), "r"(a2), "r"(a3), "r"(b0), "r"(b1));
}

// A-exchange buffer: per warp, 16 rows x 272 bytes (136 bf16; 128 used).
// a-frag LDS at byte g*272 + 32*kt + 4*tg (+16) is 32-bank conflict-free.
static constexpr int AROW = 272;
static constexpr int ABUF = 16 * AROW;   // 4352 B/warp

__global__ __launch_bounds__(128, 3)
void mlp_kernel(const float* __restrict__ x, float* __restrict__ out,
                int B, int nTiles)
{
    __shared__ ull    s_f1[512], s_f2[1024], s_f3[512], s_f4[128];
    __shared__ float2 s_sc1[64], s_sc2[32], s_sc3[32], s_sc4[8];
    __shared__ __align__(16) char s_A[4 * ABUF];

    int tid = threadIdx.x;
    for (int i = tid; i < 512; i += 128) { s_f1[i] = g_f1[i]; s_f3[i] = g_f3[i]; }
    for (int i = tid; i < 1024; i += 128) s_f2[i] = g_f2[i];
    s_f4[tid] = g_f4[tid];
    if (tid < 64) s_sc1[tid] = g_sc1[tid];
    if (tid < 32) { s_sc2[tid] = g_sc2[tid]; s_sc3[tid] = g_sc3[tid]; }
    if (tid < 8) s_sc4[tid] = g_sc4[tid];
    __syncthreads();

    int wid = tid >> 5, lane = tid & 31, g = lane >> 2, tg = lane & 3;
    char* abuf = s_A + wid * ABUF;

    for (long tile = (long)blockIdx.x * 4 + wid; tile < nTiles;
         tile += (long)gridDim.x * 4) {
        long r0 = tile * 16;
        long rA = r0 + g, rB = r0 + g + 8;
        const float* xA = x + (size_t)((rA < B) ? rA : (B - 1)) * 16;
        const float* xB = x + (size_t)((rB < B) ? rB : (B - 1)) * 16;

        // ---- L1: A from x directly (hi/lo split per element) ----
        uint32_t a00 = splitbf(xA[tg]),      a01 = splitbf(xB[tg]);
        uint32_t a02 = splitbf(xA[tg + 4]),  a03 = splitbf(xB[tg + 4]);
        uint32_t a10 = splitbf(xA[tg + 8]),  a11 = splitbf(xB[tg + 8]);
        uint32_t a12 = splitbf(xA[tg + 12]), a13 = splitbf(xB[tg + 12]);

        float c1r[8][4];
        #pragma unroll
        for (int nt = 0; nt < 8; nt++) {
            c1r[nt][0] = c1r[nt][1] = c1r[nt][2] = c1r[nt][3] = 0.0f;
            ull w0 = s_f1[nt * 32 + lane];
            ull w1 = s_f1[256 + nt * 32 + lane];
            mma16816(c1r[nt], a00, a01, a02, a03, (uint32_t)w0, (uint32_t)(w0 >> 32));
            mma16816(c1r[nt], a10, a11, a12, a13, (uint32_t)w1, (uint32_t)(w1 >> 32));
        }
        // epilogue 1 -> abuf (128 bf16 cols)
        #pragma unroll
        for (int nt = 0; nt < 8; nt++) {
            int ch = 8 * nt + 2 * tg;
            float2 s0 = s_sc1[ch], s1 = s_sc1[ch + 1];
            float h00 = fmaxf(fmaf(c1r[nt][0], s0.x, s0.y), 0.0f);
            float h01 = fmaxf(fmaf(c1r[nt][1], s1.x, s1.y), 0.0f);
            float h10 = fmaxf(fmaf(c1r[nt][2], s0.x, s0.y), 0.0f);
            float h11 = fmaxf(fmaf(c1r[nt][3], s1.x, s1.y), 0.0f);
            int off = 32 * nt + 8 * tg;
            *(ull*)(abuf + g * AROW + off) =
                (ull)splitbf(h00) | ((ull)splitbf(h01) << 32);
            *(ull*)(abuf + (g + 8) * AROW + off) =
                (ull)splitbf(h10) | ((ull)splitbf(h11) << 32);
        }
        __syncwarp();

        // ---- L2: K=128 ----
        uint32_t a2r[8][4];
        #pragma unroll
        for (int kt = 0; kt < 8; kt++) {
            int c0 = 32 * kt + 4 * tg;
            a2r[kt][0] = *(uint32_t*)(abuf + g * AROW + c0);
            a2r[kt][1] = *(uint32_t*)(abuf + (g + 8) * AROW + c0);
            a2r[kt][2] = *(uint32_t*)(abuf + g * AROW + c0 + 16);
            a2r[kt][3] = *(uint32_t*)(abuf + (g + 8) * AROW + c0 + 16);
        }
        __syncwarp();
        float c2r[4][4];
        #pragma unroll
        for (int nt = 0; nt < 4; nt++) {
            c2r[nt][0] = c2r[nt][1] = c2r[nt][2] = c2r[nt][3] = 0.0f;
            #pragma unroll
            for (int kt = 0; kt < 8; kt++) {
                ull w = s_f2[(kt * 4 + nt) * 32 + lane];
                mma16816(c2r[nt], a2r[kt][0], a2r[kt][1], a2r[kt][2], a2r[kt][3],
                         (uint32_t)w, (uint32_t)(w >> 32));
            }
        }
        #pragma unroll
        for (int nt = 0; nt < 4; nt++) {
            int ch = 8 * nt + 2 * tg;
            float2 s0 = s_sc2[ch], s1 = s_sc2[ch + 1];
            float h00 = fmaxf(fmaf(c2r[nt][0], s0.x, s0.y), 0.0f);
            float h01 = fmaxf(fmaf(c2r[nt][1], s1.x, s1.y), 0.0f);
            float h10 = fmaxf(fmaf(c2r[nt][2], s0.x, s0.y), 0.0f);
            float h11 = fmaxf(fmaf(c2r[nt][3], s1.x, s1.y), 0.0f);
            int off = 32 * nt + 8 * tg;
            *(ull*)(abuf + g * AROW + off) =
                (ull)splitbf(h00) | ((ull)splitbf(h01) << 32);
            *(ull*)(abuf + (g + 8) * AROW + off) =
                (ull)splitbf(h10) | ((ull)splitbf(h11) << 32);
        }
        __syncwarp();

        // ---- L3: K=64 ----
        uint32_t a3r[4][4];
        #pragma unroll
        for (int kt = 0; kt < 4; kt++) {
            int c0 = 32 * kt + 4 * tg;
            a3r[kt][0] = *(uint32_t*)(abuf + g * AROW + c0);
            a3r[kt][1] = *(uint32_t*)(abuf + (g + 8) * AROW + c0);
            a3r[kt][2] = *(uint32_t*)(abuf + g * AROW + c0 + 16);
            a3r[kt][3] = *(uint32_t*)(abuf + (g + 8) * AROW + c0 + 16);
        }
        __syncwarp();
        float c3r[4][4];
        #pragma unroll
        for (int nt = 0; nt < 4; nt++) {
            c3r[nt][0] = c3r[nt][1] = c3r[nt][2] = c3r[nt][3] = 0.0f;
            #pragma unroll
            for (int kt = 0; kt < 4; kt++) {
                ull w = s_f3[(kt * 4 + nt) * 32 + lane];
                mma16816(c3r[nt], a3r[kt][0], a3r[kt][1], a3r[kt][2], a3r[kt][3],
                         (uint32_t)w, (uint32_t)(w >> 32));
            }
        }
        #pragma unroll
        for (int nt = 0; nt < 4; nt++) {
            int ch = 8 * nt + 2 * tg;
            float2 s0 = s_sc3[ch], s1 = s_sc3[ch + 1];
            float h00 = fmaxf(fmaf(c3r[nt][0], s0.x, s0.y), 0.0f);
            float h01 = fmaxf(fmaf(c3r[nt][1], s1.x, s1.y), 0.0f);
            float h10 = fmaxf(fmaf(c3r[nt][2], s0.x, s0.y), 0.0f);
            float h11 = fmaxf(fmaf(c3r[nt][3], s1.x, s1.y), 0.0f);
            int off = 32 * nt + 8 * tg;
            *(ull*)(abuf + g * AROW + off) =
                (ull)splitbf(h00) | ((ull)splitbf(h01) << 32);
            *(ull*)(abuf + (g + 8) * AROW + off) =
                (ull)splitbf(h10) | ((ull)splitbf(h11) << 32);
        }
        __syncwarp();

        // ---- L4: K=64, N=8 (5 real) ----
        uint32_t a4r[4][4];
        #pragma unroll
        for (int kt = 0; kt < 4; kt++) {
            int c0 = 32 * kt + 4 * tg;
            a4r[kt][0] = *(uint32_t*)(abuf + g * AROW + c0);
            a4r[kt][1] = *(uint32_t*)(abuf + (g + 8) * AROW + c0);
            a4r[kt][2] = *(uint32_t*)(abuf + g * AROW + c0 + 16);
            a4r[kt][3] = *(uint32_t*)(abuf + (g + 8) * AROW + c0 + 16);
        }
        __syncwarp();   // also protects abuf for next tile's epilogue-1 stores
        float c4[4] = {0.0f, 0.0f, 0.0f, 0.0f};
        #pragma unroll
        for (int kt = 0; kt < 4; kt++) {
            ull w = s_f4[kt * 32 + lane];
            mma16816(c4, a4r[kt][0], a4r[kt][1], a4r[kt][2], a4r[kt][3],
                     (uint32_t)w, (uint32_t)(w >> 32));
        }

        // ---- softmax over cols 0..4 (quad reduce across tg) ----
        int col0 = 2 * tg, col1 = 2 * tg + 1;
        float2 t0 = s_sc4[col0], t1 = s_sc4[col1];
        const float NEG = -1.0e30f;
        float v0 = (col0 < 5) ? fmaf(c4[0], t0.x, t0.y) : NEG;
        float v1 = (col1 < 5) ? fmaf(c4[1], t1.x, t1.y) : NEG;
        float v2 = (col0 < 5) ? fmaf(c4[2], t0.x, t0.y) : NEG;
        float v3 = (col1 < 5) ? fmaf(c4[3], t1.x, t1.y) : NEG;

        float mA = fmaxf(v0, v1), mB = fmaxf(v2, v3);
        mA = fmaxf(mA, __shfl_xor_sync(0xffffffffu, mA, 1));
        mB = fmaxf(mB, __shfl_xor_sync(0xffffffffu, mB, 1));
        mA = fmaxf(mA, __shfl_xor_sync(0xffffffffu, mA, 2));
        mB = fmaxf(mB, __shfl_xor_sync(0xffffffffu, mB, 2));
        float e0 = __expf(v0 - mA), e1 = __expf(v1 - mA);
        float e2 = __expf(v2 - mB), e3 = __expf(v3 - mB);
        float sA = e0 + e1, sB = e2 + e3;
        sA += __shfl_xor_sync(0xffffffffu, sA, 1);
        sB += __shfl_xor_sync(0xffffffffu, sB, 1);
        sA += __shfl_xor_sync(0xffffffffu, sA, 2);
        sB += __shfl_xor_sync(0xffffffffu, sB, 2);
        float iA = __fdiv_rn(1.0f, sA), iB = __fdiv_rn(1.0f, sB);

        if (rA < B) {
            float* p = out + (size_t)rA * 5;
            if (col0 < 5) p[col0] = e0 * iA;
            if (col1 < 5) p[col1] = e1 * iA;
        }
        if (rB < B) {
            float* p = out + (size_t)rB * 5;
            if (col0 < 5) p[col0] = e2 * iB;
            if (col1 < 5) p[col1] = e3 * iB;
        }
    }
}

// ---------------- launch ----------------
extern "C" void kernel_launch(void* const* d_in, const int* in_sizes, int n_in,
                              void* d_out, int out_size)
{
    const float* x  = (const float*)d_in[0];
    const float* W1 = (const float*)d_in[1];
    const float* b1 = (const float*)d_in[2];
    const float* W2 = (const float*)d_in[3];
    const float* b2 = (const float*)d_in[4];
    const float* W3 = (const float*)d_in[5];
    const float* b3 = (const float*)d_in[6];
    const float* W4 = (const float*)d_in[7];
    const float* b4 = (const float*)d_in[8];

    int B = in_sizes[0] / 16;
    int nTiles = (B + 15) / 16;

    prep_kernel<<<1, 128>>>(W1, b1, W2, b2, W3, b3, W4, b4);

    int grid = 444;                               // 3 CTAs/SM persistent
    if ((long)grid * 4 > nTiles) grid = (nTiles + 3) / 4;
    mlp_kernel<<<grid, 128>>>(x, (float*)d_out, B, nTiles);
}

// round 14
// speedup vs baseline: 2.3200x; 1.1011x over previous
#include <cuda_runtime.h>
#include <cuda_bf16.h>
#include <cstdint>

typedef unsigned long long ull;

// ================= fragment tables (device globals, filled by prep) =================
__device__ __align__(16) ull    g_f1[2 * 8 * 32];   // L1: K=32 (2 kt), N=64 (8 nt)
__device__ __align__(16) ull    g_f2[8 * 4 * 32];   // L2: K=128, N=32
__device__ __align__(16) ull    g_f3[4 * 4 * 32];   // L3: K=64,  N=32
__device__ __align__(16) ull    g_f4[4 * 1 * 32];   // L4: K=64,  N=8 (5 real)
__device__ __align__(16) float2 g_sc1[64];
__device__ __align__(16) float2 g_sc2[32];
__device__ __align__(16) float2 g_sc3[32];
__device__ __align__(16) float2 g_sc4[8];
__device__ unsigned g_ctr;                          // work-steal counter (reset by prep)

__device__ __forceinline__ uint32_t dupbf(float w) {
    uint16_t b = __bfloat16_as_ushort(__float2bfloat16(w));   // exact for |int|<=127
    return (uint32_t)b | ((uint32_t)b << 16);
}
// hi/lo double-bf16 split, packed: low16 = bf16(v), high16 = bf16(v - hi)
__device__ __forceinline__ uint32_t splitbf(float v) {
    __nv_bfloat16 h = __float2bfloat16(v);
    float hf = __bfloat162float(h);
    uint16_t hb = __bfloat16_as_ushort(h);
    uint16_t lb = __bfloat16_as_ushort(__float2bfloat16(v - hf));
    return (uint32_t)hb | ((uint32_t)lb << 16);
}

// HAWQ weight quant (exact): ws = max|W|/127 ; w_int = clip(rint(W/ws), -127, 127)
__device__ __forceinline__ float qw(float w, float ws) {
    float q = rintf(__fdiv_rn(w, ws));
    return fminf(fmaxf(q, -127.0f), 127.0f);
}

__global__ void prep_kernel(const float* __restrict__ W1, const float* __restrict__ b1,
                            const float* __restrict__ W2, const float* __restrict__ b2,
                            const float* __restrict__ W3, const float* __restrict__ b3,
                            const float* __restrict__ W4, const float* __restrict__ b4)
{
    __shared__ float sw1[64 * 16];
    __shared__ float sw2[32 * 64];
    __shared__ float sw3[32 * 32];
    __shared__ float sw4[8 * 32];
    int t = threadIdx.x;
    if (t == 0) g_ctr = 0u;                 // reset work counter each replay

    if (t < 64) {
        float m = 0.0f;
        #pragma unroll
        for (int i = 0; i < 16; i++) m = fmaxf(m, fabsf(W1[t * 16 + i]));
        float ws = __fdiv_rn(m, 127.0f);
        #pragma unroll
        for (int i = 0; i < 16; i++) sw1[t * 16 + i] = qw(W1[t * 16 + i], ws);
        g_sc1[t] = make_float2(ws, b1[t]);
    } else if (t < 96) {
        int k = t - 64;
        float m = 0.0f;
        #pragma unroll
        for (int j = 0; j < 64; j++) m = fmaxf(m, fabsf(W2[k * 64 + j]));
        float ws = __fdiv_rn(m, 127.0f);
        #pragma unroll
        for (int j = 0; j < 64; j++) sw2[k * 64 + j] = qw(W2[k * 64 + j], ws);
        g_sc2[k] = make_float2(ws, b2[k]);
    } else {
        int k = t - 96;
        float m = 0.0f;
        #pragma unroll
        for (int j = 0; j < 32; j++) m = fmaxf(m, fabsf(W3[k * 32 + j]));
        float ws = __fdiv_rn(m, 127.0f);
        #pragma unroll
        for (int j = 0; j < 32; j++) sw3[k * 32 + j] = qw(W3[k * 32 + j], ws);
        g_sc3[k] = make_float2(ws, b3[k]);
    }
    if (t < 5) {
        float m = 0.0f;
        #pragma unroll
        for (int j = 0; j < 32; j++) m = fmaxf(m, fabsf(W4[t * 32 + j]));
        float ws = __fdiv_rn(m, 127.0f);
        #pragma unroll
        for (int j = 0; j < 32; j++) sw4[t * 32 + j] = qw(W4[t * 32 + j], ws);
        g_sc4[t] = make_float2(ws, b4[t]);
    } else if (t < 8) {
        #pragma unroll
        for (int j = 0; j < 32; j++) sw4[t * 32 + j] = 0.0f;
        g_sc4[t] = make_float2(0.0f, 0.0f);
    }
    __syncthreads();

    // Fragment tables. i = ((kt*NT)+nt)*32 + lane ; n = 8*nt+g ; c0 = 8*kt+tg.
    for (int i = t; i < 512; i += 128) {       // L1
        int kt = i >> 8, rem = i & 255, nt = rem >> 5, lane = rem & 31;
        int g = lane >> 2, tg = lane & 3, n = 8 * nt + g, c0 = 8 * kt + tg;
        g_f1[i] = (ull)dupbf(sw1[n * 16 + c0]) | ((ull)dupbf(sw1[n * 16 + c0 + 4]) << 32);
    }
    for (int i = t; i < 1024; i += 128) {      // L2
        int kt = i >> 7, rem = i & 127, nt = rem >> 5, lane = rem & 31;
        int g = lane >> 2, tg = lane & 3, n = 8 * nt + g, c0 = 8 * kt + tg;
        g_f2[i] = (ull)dupbf(sw2[n * 64 + c0]) | ((ull)dupbf(sw2[n * 64 + c0 + 4]) << 32);
    }
    for (int i = t; i < 512; i += 128) {       // L3
        int kt = i >> 7, rem = i & 127, nt = rem >> 5, lane = rem & 31;
        int g = lane >> 2, tg = lane & 3, n = 8 * nt + g, c0 = 8 * kt + tg;
        g_f3[i] = (ull)dupbf(sw3[n * 32 + c0]) | ((ull)dupbf(sw3[n * 32 + c0 + 4]) << 32);
    }
    if (t < 128) {                              // L4
        int kt = t >> 5, lane = t & 31;
        int g = lane >> 2, tg = lane & 3, n = g, c0 = 8 * kt + tg;
        g_f4[t] = (ull)dupbf(sw4[n * 32 + c0]) | ((ull)dupbf(sw4[n * 32 + c0 + 4]) << 32);
    }
}

// ================= mma.sync m16n8k16 bf16 =================
__device__ __forceinline__ void mma16816(float* c, uint32_t a0, uint32_t a1,
                                         uint32_t a2, uint32_t a3,
                                         uint32_t b0, uint32_t b1) {
    asm volatile(
        "mma.sync.aligned.m16n8k16.row.col.f32.bf16.bf16.f32 "
        "{%0,%1,%2,%3}, {%4,%5,%6,%7}, {%8,%9}, {%0,%1,%2,%3};"
        : "+f"(c[0]), "+f"(c[1]), "+f"(c[2]), "+f"(c[3])
        : "r"(a0), "r"(a1), "r"(a2), "r"(a3), "r"(b0), "r"(b1));
}

// A-exchange buffer: 16 rows x 272 bytes per tile (conflict-free for frag access).
static constexpr int AROW = 272;
static constexpr int ABUF = 16 * AROW;   // 4352 B per tile buffer
static constexpr int DYN_SMEM = 4 * 2 * ABUF;   // 34816 B

__global__ __launch_bounds__(128, 3)
void mlp_kernel(const float* __restrict__ x, float* __restrict__ out,
                int B, int nPairs)
{
    __shared__ ull    s_f1[512], s_f2[1024], s_f3[512], s_f4[128];
    __shared__ float2 s_sc1[64], s_sc2[32], s_sc3[32], s_sc4[8];
    extern __shared__ __align__(16) char s_A[];    // 4 warps x 2 tiles x ABUF

    int tid = threadIdx.x;
    for (int i = tid; i < 512; i += 128) { s_f1[i] = g_f1[i]; s_f3[i] = g_f3[i]; }
    for (int i = tid; i < 1024; i += 128) s_f2[i] = g_f2[i];
    s_f4[tid] = g_f4[tid];
    if (tid < 64) s_sc1[tid] = g_sc1[tid];
    if (tid < 32) { s_sc2[tid] = g_sc2[tid]; s_sc3[tid] = g_sc3[tid]; }
    if (tid < 8) s_sc4[tid] = g_sc4[tid];
    __syncthreads();

    int wid = tid >> 5, lane = tid & 31, g = lane >> 2, tg = lane & 3;
    char* ab[2];
    ab[0] = s_A + (wid * 2) * ABUF;
    ab[1] = ab[0] + ABUF;

    unsigned p;
    if (lane == 0) p = atomicAdd(&g_ctr, 1u);
    p = __shfl_sync(0xffffffffu, p, 0);

    while (p < (unsigned)nPairs) {
        // ---- load inputs for both tiles (hi/lo split) ----
        uint32_t ax[2][8];
        long rAg[2], rBg[2];
        #pragma unroll
        for (int u = 0; u < 2; u++) {
            long r0 = ((long)p * 2 + u) * 16;
            long rA = r0 + g, rB = r0 + g + 8;
            rAg[u] = rA; rBg[u] = rB;
            const float* xA = x + (size_t)((rA < B) ? rA : (B - 1)) * 16;
            const float* xB = x + (size_t)((rB < B) ? rB : (B - 1)) * 16;
            ax[u][0] = splitbf(xA[tg]);      ax[u][1] = splitbf(xB[tg]);
            ax[u][2] = splitbf(xA[tg + 4]);  ax[u][3] = splitbf(xB[tg + 4]);
            ax[u][4] = splitbf(xA[tg + 8]);  ax[u][5] = splitbf(xB[tg + 8]);
            ax[u][6] = splitbf(xA[tg + 12]); ax[u][7] = splitbf(xB[tg + 12]);
        }

        // ---- L1: per-nt compute + fused epilogue -> abuf ----
        #pragma unroll
        for (int nt = 0; nt < 8; nt++) {
            ull w0 = s_f1[nt * 32 + lane];
            ull w1 = s_f1[256 + nt * 32 + lane];
            int ch = 8 * nt + 2 * tg;
            float2 s0 = s_sc1[ch], s1 = s_sc1[ch + 1];
            int off = 32 * nt + 8 * tg;
            #pragma unroll
            for (int u = 0; u < 2; u++) {
                float c[4] = {0.0f, 0.0f, 0.0f, 0.0f};
                mma16816(c, ax[u][0], ax[u][1], ax[u][2], ax[u][3],
                         (uint32_t)w0, (uint32_t)(w0 >> 32));
                mma16816(c, ax[u][4], ax[u][5], ax[u][6], ax[u][7],
                         (uint32_t)w1, (uint32_t)(w1 >> 32));
                float h00 = fmaxf(fmaf(c[0], s0.x, s0.y), 0.0f);
                float h01 = fmaxf(fmaf(c[1], s1.x, s1.y), 0.0f);
                float h10 = fmaxf(fmaf(c[2], s0.x, s0.y), 0.0f);
                float h11 = fmaxf(fmaf(c[3], s1.x, s1.y), 0.0f);
                *(ull*)(ab[u] + g * AROW + off) =
                    (ull)splitbf(h00) | ((ull)splitbf(h01) << 32);
                *(ull*)(ab[u] + (g + 8) * AROW + off) =
                    (ull)splitbf(h10) | ((ull)splitbf(h11) << 32);
            }
        }
        __syncwarp();

        // ---- L2: K=128, kt-outer, JIT a-frags, shared weight loads ----
        float c2[2][4][4];
        #pragma unroll
        for (int u = 0; u < 2; u++)
            #pragma unroll
            for (int nt = 0; nt < 4; nt++)
                c2[u][nt][0] = c2[u][nt][1] = c2[u][nt][2] = c2[u][nt][3] = 0.0f;
        #pragma unroll
        for (int kt = 0; kt < 8; kt++) {
            uint32_t a[2][4];
            int c0 = 32 * kt + 4 * tg;
            #pragma unroll
            for (int u = 0; u < 2; u++) {
                a[u][0] = *(uint32_t*)(ab[u] + g * AROW + c0);
                a[u][1] = *(uint32_t*)(ab[u] + (g + 8) * AROW + c0);
                a[u][2] = *(uint32_t*)(ab[u] + g * AROW + c0 + 16);
                a[u][3] = *(uint32_t*)(ab[u] + (g + 8) * AROW + c0 + 16);
            }
            #pragma unroll
            for (int nt = 0; nt < 4; nt++) {
                ull w = s_f2[(kt * 4 + nt) * 32 + lane];
                mma16816(c2[0][nt], a[0][0], a[0][1], a[0][2], a[0][3],
                         (uint32_t)w, (uint32_t)(w >> 32));
                mma16816(c2[1][nt], a[1][0], a[1][1], a[1][2], a[1][3],
                         (uint32_t)w, (uint32_t)(w >> 32));
            }
        }
        __syncwarp();
        #pragma unroll
        for (int nt = 0; nt < 4; nt++) {
            int ch = 8 * nt + 2 * tg;
            float2 s0 = s_sc2[ch], s1 = s_sc2[ch + 1];
            int off = 32 * nt + 8 * tg;
            #pragma unroll
            for (int u = 0; u < 2; u++) {
                float h00 = fmaxf(fmaf(c2[u][nt][0], s0.x, s0.y), 0.0f);
                float h01 = fmaxf(fmaf(c2[u][nt][1], s1.x, s1.y), 0.0f);
                float h10 = fmaxf(fmaf(c2[u][nt][2], s0.x, s0.y), 0.0f);
                float h11 = fmaxf(fmaf(c2[u][nt][3], s1.x, s1.y), 0.0f);
                *(ull*)(ab[u] + g * AROW + off) =
                    (ull)splitbf(h00) | ((ull)splitbf(h01) << 32);
                *(ull*)(ab[u] + (g + 8) * AROW + off) =
                    (ull)splitbf(h10) | ((ull)splitbf(h11) << 32);
            }
        }
        __syncwarp();

        // ---- L3: K=64 ----
        float c3[2][4][4];
        #pragma unroll
        for (int u = 0; u < 2; u++)
            #pragma unroll
            for (int nt = 0; nt < 4; nt++)
                c3[u][nt][0] = c3[u][nt][1] = c3[u][nt][2] = c3[u][nt][3] = 0.0f;
        #pragma unroll
        for (int kt = 0; kt < 4; kt++) {
            uint32_t a[2][4];
            int c0 = 32 * kt + 4 * tg;
            #pragma unroll
            for (int u = 0; u < 2; u++) {
                a[u][0] = *(uint32_t*)(ab[u] + g * AROW + c0);
                a[u][1] = *(uint32_t*)(ab[u] + (g + 8) * AROW + c0);
                a[u][2] = *(uint32_t*)(ab[u] + g * AROW + c0 + 16);
                a[u][3] = *(uint32_t*)(ab[u] + (g + 8) * AROW + c0 + 16);
            }
            #pragma unroll
            for (int nt = 0; nt < 4; nt++) {
                ull w = s_f3[(kt * 4 + nt) * 32 + lane];
                mma16816(c3[0][nt], a[0][0], a[0][1], a[0][2], a[0][3],
                         (uint32_t)w, (uint32_t)(w >> 32));
                mma16816(c3[1][nt], a[1][0], a[1][1], a[1][2], a[1][3],
                         (uint32_t)w, (uint32_t)(w >> 32));
            }
        }
        __syncwarp();
        #pragma unroll
        for (int nt = 0; nt < 4; nt++) {
            int ch = 8 * nt + 2 * tg;
            float2 s0 = s_sc3[ch], s1 = s_sc3[ch + 1];
            int off = 32 * nt + 8 * tg;
            #pragma unroll
            for (int u = 0; u < 2; u++) {
                float h00 = fmaxf(fmaf(c3[u][nt][0], s0.x, s0.y), 0.0f);
                float h01 = fmaxf(fmaf(c3[u][nt][1], s1.x, s1.y), 0.0f);
                float h10 = fmaxf(fmaf(c3[u][nt][2], s0.x, s0.y), 0.0f);
                float h11 = fmaxf(fmaf(c3[u][nt][3], s1.x, s1.y), 0.0f);
                *(ull*)(ab[u] + g * AROW + off) =
                    (ull)splitbf(h00) | ((ull)splitbf(h01) << 32);
                *(ull*)(ab[u] + (g + 8) * AROW + off) =
                    (ull)splitbf(h10) | ((ull)splitbf(h11) << 32);
            }
        }
        __syncwarp();

        // ---- L4: K=64, N=8 (5 real) ----
        float c4[2][4];
        c4[0][0] = c4[0][1] = c4[0][2] = c4[0][3] = 0.0f;
        c4[1][0] = c4[1][1] = c4[1][2] = c4[1][3] = 0.0f;
        #pragma unroll
        for (int kt = 0; kt < 4; kt++) {
            uint32_t a[2][4];
            int c0 = 32 * kt + 4 * tg;
            #pragma unroll
            for (int u = 0; u < 2; u++) {
                a[u][0] = *(uint32_t*)(ab[u] + g * AROW + c0);
                a[u][1] = *(uint32_t*)(ab[u] + (g + 8) * AROW + c0);
                a[u][2] = *(uint32_t*)(ab[u] + g * AROW + c0 + 16);
                a[u][3] = *(uint32_t*)(ab[u] + (g + 8) * AROW + c0 + 16);
            }
            ull w = s_f4[kt * 32 + lane];
            mma16816(c4[0], a[0][0], a[0][1], a[0][2], a[0][3],
                     (uint32_t)w, (uint32_t)(w >> 32));
            mma16816(c4[1], a[1][0], a[1][1], a[1][2], a[1][3],
                     (uint32_t)w, (uint32_t)(w >> 32));
        }
        __syncwarp();   // abuf reads done before next pair's L1 epilogue writes

        // ---- softmax + store per tile ----
        int col0 = 2 * tg, col1 = 2 * tg + 1;
        float2 t0 = s_sc4[col0], t1 = s_sc4[col1];
        const float NEG = -1.0e30f;
        #pragma unroll
        for (int u = 0; u < 2; u++) {
            float v0 = (col0 < 5) ? fmaf(c4[u][0], t0.x, t0.y) : NEG;
            float v1 = (col1 < 5) ? fmaf(c4[u][1], t1.x, t1.y) : NEG;
            float v2 = (col0 < 5) ? fmaf(c4[u][2], t0.x, t0.y) : NEG;
            float v3 = (col1 < 5) ? fmaf(c4[u][3], t1.x, t1.y) : NEG;

            float mA = fmaxf(v0, v1), mB = fmaxf(v2, v3);
            mA = fmaxf(mA, __shfl_xor_sync(0xffffffffu, mA, 1));
            mB = fmaxf(mB, __shfl_xor_sync(0xffffffffu, mB, 1));
            mA = fmaxf(mA, __shfl_xor_sync(0xffffffffu, mA, 2));
            mB = fmaxf(mB, __shfl_xor_sync(0xffffffffu, mB, 2));
            float e0 = __expf(v0 - mA), e1 = __expf(v1 - mA);
            float e2 = __expf(v2 - mB), e3 = __expf(v3 - mB);
            float sA = e0 + e1, sB = e2 + e3;
            sA += __shfl_xor_sync(0xffffffffu, sA, 1);
            sB += __shfl_xor_sync(0xffffffffu, sB, 1);
            sA += __shfl_xor_sync(0xffffffffu, sA, 2);
            sB += __shfl_xor_sync(0xffffffffu, sB, 2);
            float iA = __fdiv_rn(1.0f, sA), iB = __fdiv_rn(1.0f, sB);

            if (rAg[u] < B) {
                float* q = out + (size_t)rAg[u] * 5;
                if (col0 < 5) q[col0] = e0 * iA;
                if (col1 < 5) q[col1] = e1 * iA;
            }
            if (rBg[u] < B) {
                float* q = out + (size_t)rBg[u] * 5;
                if (col0 < 5) q[col0] = e2 * iB;
                if (col1 < 5) q[col1] = e3 * iB;
            }
        }

        if (lane == 0) p = atomicAdd(&g_ctr, 1u);
        p = __shfl_sync(0xffffffffu, p, 0);
    }
}

// ---------------- launch ----------------
extern "C" void kernel_launch(void* const* d_in, const int* in_sizes, int n_in,
                              void* d_out, int out_size)
{
    const float* x  = (const float*)d_in[0];
    const float* W1 = (const float*)d_in[1];
    const float* b1 = (const float*)d_in[2];
    const float* W2 = (const float*)d_in[3];
    const float* b2 = (const float*)d_in[4];
    const float* W3 = (const float*)d_in[5];
    const float* b3 = (const float*)d_in[6];
    const float* W4 = (const float*)d_in[7];
    const float* b4 = (const float*)d_in[8];

    int B = in_sizes[0] / 16;
    int nTiles = (B + 15) / 16;
    int nPairs = (nTiles + 1) / 2;

    // Opt-in: static (~18.5K) + dynamic (34816) exceeds the 48K default launch
    // limit. Host-side attribute set; not a stream op, so capture-neutral.
    cudaFuncSetAttribute(mlp_kernel, cudaFuncAttributeMaxDynamicSharedMemorySize,
                         DYN_SMEM);

    prep_kernel<<<1, 128>>>(W1, b1, W2, b2, W3, b3, W4, b4);

    int grid = 444;                               // 3 CTAs/SM persistent + work stealing
    if (grid > nPairs) grid = nPairs;
    mlp_kernel<<<grid, 128, DYN_SMEM>>>(x, (float*)d_out, B, nPairs);
}

// round 15
// speedup vs baseline: 3.8996x; 1.6809x over previous
#include <cuda_runtime.h>
#include <cuda_bf16.h>
#include <cstdint>

typedef unsigned long long ull;

// ================= fragment tables (device globals, filled by prep) =================
// Register-chained layout: next-layer K ordering == previous-layer channel order.
// b-word pair per (ktile, ntile, lane): b0 = (w[n][ch0], w[n][ch0+1]) bf16x2,
// b1 = (w[n][ch0+8], w[n][ch0+9]) ; ch0 = 16*kt + 2*tg ; n = 8*nt + g.
__device__ __align__(16) ull    g_f1[8 * 32];        // L1: 1 ktile (K=16ch), 8 nt
__device__ __align__(16) ull    g_f2[4 * 4 * 32];    // L2: 4 kt (64ch), 4 nt
__device__ __align__(16) ull    g_f3[2 * 4 * 32];    // L3: 2 kt (32ch), 4 nt
__device__ __align__(16) ull    g_f4[2 * 1 * 32];    // L4: 2 kt (32ch), 1 nt (5 real cols)
__device__ __align__(16) float2 g_sc1[64];
__device__ __align__(16) float2 g_sc2[32];
__device__ __align__(16) float2 g_sc3[32];
__device__ __align__(16) float2 g_sc4[8];
__device__ unsigned g_ctr;                           // work-steal counter (reset by prep)

// pack two floats as bf16x2: LOW half = a (even/first-k), HIGH = b
__device__ __forceinline__ uint32_t pk2bf(float a, float b) {
    uint32_t r;
    asm("cvt.rn.bf16x2.f32 %0, %1, %2;" : "=r"(r) : "f"(b), "f"(a));
    return r;
}
// hi/lo double-bf16 split of a pair: hi = bf16x2(e,o); lo = residuals
__device__ __forceinline__ void pack_hilo(float e, float o, uint32_t& hi, uint32_t& lo) {
    hi = pk2bf(e, o);
    float ef = __uint_as_float(hi << 16);
    float of = __uint_as_float(hi & 0xFFFF0000u);
    lo = pk2bf(e - ef, o - of);
}

// HAWQ weight quant (exact): ws = max|W|/127 ; w_int = clip(rint(W/ws), -127, 127)
__device__ __forceinline__ float qw(float w, float ws) {
    float q = rintf(__fdiv_rn(w, ws));
    return fminf(fmaxf(q, -127.0f), 127.0f);
}

__global__ void prep_kernel(const float* __restrict__ W1, const float* __restrict__ b1,
                            const float* __restrict__ W2, const float* __restrict__ b2,
                            const float* __restrict__ W3, const float* __restrict__ b3,
                            const float* __restrict__ W4, const float* __restrict__ b4)
{
    __shared__ float sw1[64 * 16];
    __shared__ float sw2[32 * 64];
    __shared__ float sw3[32 * 32];
    __shared__ float sw4[8 * 32];
    int t = threadIdx.x;
    if (t == 0) g_ctr = 0u;                 // reset work counter each replay

    if (t < 64) {
        float m = 0.0f;
        #pragma unroll
        for (int i = 0; i < 16; i++) m = fmaxf(m, fabsf(W1[t * 16 + i]));
        float ws = __fdiv_rn(m, 127.0f);
        #pragma unroll
        for (int i = 0; i < 16; i++) sw1[t * 16 + i] = qw(W1[t * 16 + i], ws);
        g_sc1[t] = make_float2(ws, b1[t]);
    } else if (t < 96) {
        int k = t - 64;
        float m = 0.0f;
        #pragma unroll
        for (int j = 0; j < 64; j++) m = fmaxf(m, fabsf(W2[k * 64 + j]));
        float ws = __fdiv_rn(m, 127.0f);
        #pragma unroll
        for (int j = 0; j < 64; j++) sw2[k * 64 + j] = qw(W2[k * 64 + j], ws);
        g_sc2[k] = make_float2(ws, b2[k]);
    } else {
        int k = t - 96;
        float m = 0.0f;
        #pragma unroll
        for (int j = 0; j < 32; j++) m = fmaxf(m, fabsf(W3[k * 32 + j]));
        float ws = __fdiv_rn(m, 127.0f);
        #pragma unroll
        for (int j = 0; j < 32; j++) sw3[k * 32 + j] = qw(W3[k * 32 + j], ws);
        g_sc3[k] = make_float2(ws, b3[k]);
    }
    if (t < 5) {
        float m = 0.0f;
        #pragma unroll
        for (int j = 0; j < 32; j++) m = fmaxf(m, fabsf(W4[t * 32 + j]));
        float ws = __fdiv_rn(m, 127.0f);
        #pragma unroll
        for (int j = 0; j < 32; j++) sw4[t * 32 + j] = qw(W4[t * 32 + j], ws);
        g_sc4[t] = make_float2(ws, b4[t]);
    } else if (t < 8) {
        #pragma unroll
        for (int j = 0; j < 32; j++) sw4[t * 32 + j] = 0.0f;
        g_sc4[t] = make_float2(0.0f, 0.0f);
    }
    __syncthreads();

    // --- fragment tables (direct-channel layout) ---
    // helper mapping per entry index i: lane = i & 31 ; g = lane>>2 ; tg = lane&3
    for (int i = t; i < 8 * 32; i += 128) {                 // L1: nt = i>>5
        int nt = i >> 5, lane = i & 31, g = lane >> 2, tg = lane & 3;
        int n = 8 * nt + g;
        uint32_t b0 = pk2bf(sw1[n * 16 + 2 * tg],     sw1[n * 16 + 2 * tg + 1]);
        uint32_t b1 = pk2bf(sw1[n * 16 + 2 * tg + 8], sw1[n * 16 + 2 * tg + 9]);
        g_f1[i] = (ull)b0 | ((ull)b1 << 32);
    }
    for (int i = t; i < 16 * 32; i += 128) {                // L2: (kt*4+nt) = i>>5
        int e = i >> 5, kt = e >> 2, nt = e & 3, lane = i & 31;
        int g = lane >> 2, tg = lane & 3, n = 8 * nt + g, ch = 16 * kt + 2 * tg;
        uint32_t b0 = pk2bf(sw2[n * 64 + ch],     sw2[n * 64 + ch + 1]);
        uint32_t b1 = pk2bf(sw2[n * 64 + ch + 8], sw2[n * 64 + ch + 9]);
        g_f2[i] = (ull)b0 | ((ull)b1 << 32);
    }
    for (int i = t; i < 8 * 32; i += 128) {                 // L3
        int e = i >> 5, kt = e >> 2, nt = e & 3, lane = i & 31;
        int g = lane >> 2, tg = lane & 3, n = 8 * nt + g, ch = 16 * kt + 2 * tg;
        uint32_t b0 = pk2bf(sw3[n * 32 + ch],     sw3[n * 32 + ch + 1]);
        uint32_t b1 = pk2bf(sw3[n * 32 + ch + 8], sw3[n * 32 + ch + 9]);
        g_f3[i] = (ull)b0 | ((ull)b1 << 32);
    }
    if (t < 64) {                                           // L4: kt = t>>5
        int kt = t >> 5, lane = t & 31, g = lane >> 2, tg = lane & 3;
        int n = g, ch = 16 * kt + 2 * tg;
        uint32_t b0 = pk2bf(sw4[n * 32 + ch],     sw4[n * 32 + ch + 1]);
        uint32_t b1 = pk2bf(sw4[n * 32 + ch + 8], sw4[n * 32 + ch + 9]);
        g_f4[t] = (ull)b0 | ((ull)b1 << 32);
    }
}

// ================= mma.sync m16n8k16 bf16 =================
__device__ __forceinline__ void mma16816(float* c, uint32_t a0, uint32_t a1,
                                         uint32_t a2, uint32_t a3,
                                         uint32_t b0, uint32_t b1) {
    asm volatile(
        "mma.sync.aligned.m16n8k16.row.col.f32.bf16.bf16.f32 "
        "{%0,%1,%2,%3}, {%4,%5,%6,%7}, {%8,%9}, {%0,%1,%2,%3};"
        : "+f"(c[0]), "+f"(c[1]), "+f"(c[2]), "+f"(c[3])
        : "r"(a0), "r"(a1), "r"(a2), "r"(a3), "r"(b0), "r"(b1));
}

__global__ __launch_bounds__(128, 3)
void mlp_kernel(const float* __restrict__ x, float* __restrict__ out,
                int B, int nPairs)
{
    __shared__ ull    s_f1[256], s_f2[512], s_f3[256], s_f4[64];
    __shared__ float2 s_sc1[64], s_sc2[32], s_sc3[32], s_sc4[8];

    int tid = threadIdx.x;
    for (int i = tid; i < 256; i += 128) { s_f1[i] = g_f1[i]; s_f3[i] = g_f3[i]; }
    for (int i = tid; i < 512; i += 128) s_f2[i] = g_f2[i];
    if (tid < 64) { s_f4[tid] = g_f4[tid]; s_sc1[tid] = g_sc1[tid]; }
    if (tid < 32) { s_sc2[tid] = g_sc2[tid]; s_sc3[tid] = g_sc3[tid]; }
    if (tid < 8) s_sc4[tid] = g_sc4[tid];
    __syncthreads();

    int lane = tid & 31, g = lane >> 2, tg = lane & 3;

    unsigned p;
    if (lane == 0) p = atomicAdd(&g_ctr, 1u);
    p = __shfl_sync(0xffffffffu, p, 0);

    while (p < (unsigned)nPairs) {
        long rAg[2], rBg[2];
        uint32_t xhi[2][4], xlo[2][4];
        #pragma unroll
        for (int u = 0; u < 2; u++) {
            long r0 = ((long)p * 2 + u) * 16;
            long rA = r0 + g, rB = r0 + g + 8;
            rAg[u] = rA; rBg[u] = rB;
            const float* xA = x + (size_t)((rA < B) ? rA : (B - 1)) * 16;
            const float* xB = x + (size_t)((rB < B) ? rB : (B - 1)) * 16;
            float2 pa0 = *(const float2*)(xA + 2 * tg);
            float2 pa1 = *(const float2*)(xA + 2 * tg + 8);
            float2 pb0 = *(const float2*)(xB + 2 * tg);
            float2 pb1 = *(const float2*)(xB + 2 * tg + 8);
            pack_hilo(pa0.x, pa0.y, xhi[u][0], xlo[u][0]);   // a0: row g,  k=2tg..
            pack_hilo(pb0.x, pb0.y, xhi[u][1], xlo[u][1]);   // a1: row g+8
            pack_hilo(pa1.x, pa1.y, xhi[u][2], xlo[u][2]);   // a2: row g,  k=2tg+8..
            pack_hilo(pb1.x, pb1.y, xhi[u][3], xlo[u][3]);   // a3: row g+8
        }

        // ---- L1 (K=16ch, hi+lo passes) -> next A frags in registers ----
        uint2 phi[2][8], plo[2][8];
        #pragma unroll
        for (int nt = 0; nt < 8; nt++) {
            ull w = s_f1[nt * 32 + lane];
            uint32_t w0 = (uint32_t)w, w1 = (uint32_t)(w >> 32);
            int ch = 8 * nt + 2 * tg;
            float2 s0 = s_sc1[ch], s1 = s_sc1[ch + 1];
            #pragma unroll
            for (int u = 0; u < 2; u++) {
                float c[4] = {0.0f, 0.0f, 0.0f, 0.0f};
                mma16816(c, xhi[u][0], xhi[u][1], xhi[u][2], xhi[u][3], w0, w1);
                mma16816(c, xlo[u][0], xlo[u][1], xlo[u][2], xlo[u][3], w0, w1);
                float h0 = fmaxf(fmaf(c[0], s0.x, s0.y), 0.0f);
                float h1 = fmaxf(fmaf(c[1], s1.x, s1.y), 0.0f);
                float h2 = fmaxf(fmaf(c[2], s0.x, s0.y), 0.0f);
                float h3 = fmaxf(fmaf(c[3], s1.x, s1.y), 0.0f);
                uint32_t hA, lA, hB, lB;
                pack_hilo(h0, h1, hA, lA);      // row g
                pack_hilo(h2, h3, hB, lB);      // row g+8
                phi[u][nt] = make_uint2(hA, hB);
                plo[u][nt] = make_uint2(lA, lB);
            }
        }

        // ---- L2 (K=64ch = 4 ktiles) ----
        float c2[2][4][4];
        #pragma unroll
        for (int u = 0; u < 2; u++)
            #pragma unroll
            for (int nt = 0; nt < 4; nt++)
                c2[u][nt][0] = c2[u][nt][1] = c2[u][nt][2] = c2[u][nt][3] = 0.0f;
        #pragma unroll
        for (int kt = 0; kt < 4; kt++) {
            #pragma unroll
            for (int nt = 0; nt < 4; nt++) {
                ull w = s_f2[(kt * 4 + nt) * 32 + lane];
                uint32_t w0 = (uint32_t)w, w1 = (uint32_t)(w >> 32);
                #pragma unroll
                for (int u = 0; u < 2; u++) {
                    mma16816(c2[u][nt], phi[u][2 * kt].x, phi[u][2 * kt].y,
                             phi[u][2 * kt + 1].x, phi[u][2 * kt + 1].y, w0, w1);
                    mma16816(c2[u][nt], plo[u][2 * kt].x, plo[u][2 * kt].y,
                             plo[u][2 * kt + 1].x, plo[u][2 * kt + 1].y, w0, w1);
                }
            }
        }
        uint2 qhi[2][4], qlo[2][4];
        #pragma unroll
        for (int nt = 0; nt < 4; nt++) {
            int ch = 8 * nt + 2 * tg;
            float2 s0 = s_sc2[ch], s1 = s_sc2[ch + 1];
            #pragma unroll
            for (int u = 0; u < 2; u++) {
                float h0 = fmaxf(fmaf(c2[u][nt][0], s0.x, s0.y), 0.0f);
                float h1 = fmaxf(fmaf(c2[u][nt][1], s1.x, s1.y), 0.0f);
                float h2 = fmaxf(fmaf(c2[u][nt][2], s0.x, s0.y), 0.0f);
                float h3 = fmaxf(fmaf(c2[u][nt][3], s1.x, s1.y), 0.0f);
                uint32_t hA, lA, hB, lB;
                pack_hilo(h0, h1, hA, lA);
                pack_hilo(h2, h3, hB, lB);
                qhi[u][nt] = make_uint2(hA, hB);
                qlo[u][nt] = make_uint2(lA, lB);
            }
        }

        // ---- L3 (K=32ch = 2 ktiles) ----
        float c3[2][4][4];
        #pragma unroll
        for (int u = 0; u < 2; u++)
            #pragma unroll
            for (int nt = 0; nt < 4; nt++)
                c3[u][nt][0] = c3[u][nt][1] = c3[u][nt][2] = c3[u][nt][3] = 0.0f;
        #pragma unroll
        for (int kt = 0; kt < 2; kt++) {
            #pragma unroll
            for (int nt = 0; nt < 4; nt++) {
                ull w = s_f3[(kt * 4 + nt) * 32 + lane];
                uint32_t w0 = (uint32_t)w, w1 = (uint32_t)(w >> 32);
                #pragma unroll
                for (int u = 0; u < 2; u++) {
                    mma16816(c3[u][nt], qhi[u][2 * kt].x, qhi[u][2 * kt].y,
                             qhi[u][2 * kt + 1].x, qhi[u][2 * kt + 1].y, w0, w1);
                    mma16816(c3[u][nt], qlo[u][2 * kt].x, qlo[u][2 * kt].y,
                             qlo[u][2 * kt + 1].x, qlo[u][2 * kt + 1].y, w0, w1);
                }
            }
        }
        uint2 rhi[2][4], rlo[2][4];
        #pragma unroll
        for (int nt = 0; nt < 4; nt++) {
            int ch = 8 * nt + 2 * tg;
            float2 s0 = s_sc3[ch], s1 = s_sc3[ch + 1];
            #pragma unroll
            for (int u = 0; u < 2; u++) {
                float h0 = fmaxf(fmaf(c3[u][nt][0], s0.x, s0.y), 0.0f);
                float h1 = fmaxf(fmaf(c3[u][nt][1], s1.x, s1.y), 0.0f);
                float h2 = fmaxf(fmaf(c3[u][nt][2], s0.x, s0.y), 0.0f);
                float h3 = fmaxf(fmaf(c3[u][nt][3], s1.x, s1.y), 0.0f);
                uint32_t hA, lA, hB, lB;
                pack_hilo(h0, h1, hA, lA);
                pack_hilo(h2, h3, hB, lB);
                rhi[u][nt] = make_uint2(hA, hB);
                rlo[u][nt] = make_uint2(lA, lB);
            }
        }

        // ---- L4 (K=32ch = 2 ktiles, N=8 with 5 real) ----
        float c4[2][4];
        c4[0][0] = c4[0][1] = c4[0][2] = c4[0][3] = 0.0f;
        c4[1][0] = c4[1][1] = c4[1][2] = c4[1][3] = 0.0f;
        #pragma unroll
        for (int kt = 0; kt < 2; kt++) {
            ull w = s_f4[kt * 32 + lane];
            uint32_t w0 = (uint32_t)w, w1 = (uint32_t)(w >> 32);
            #pragma unroll
            for (int u = 0; u < 2; u++) {
                mma16816(c4[u], rhi[u][2 * kt].x, rhi[u][2 * kt].y,
                         rhi[u][2 * kt + 1].x, rhi[u][2 * kt + 1].y, w0, w1);
                mma16816(c4[u], rlo[u][2 * kt].x, rlo[u][2 * kt].y,
                         rlo[u][2 * kt + 1].x, rlo[u][2 * kt + 1].y, w0, w1);
            }
        }

        // ---- softmax over cols 0..4 (quad reduce) + store ----
        int col0 = 2 * tg, col1 = 2 * tg + 1;
        float2 t0 = s_sc4[col0], t1 = s_sc4[col1];
        const float NEG = -1.0e30f;
        #pragma unroll
        for (int u = 0; u < 2; u++) {
            float v0 = (col0 < 5) ? fmaf(c4[u][0], t0.x, t0.y) : NEG;
            float v1 = (col1 < 5) ? fmaf(c4[u][1], t1.x, t1.y) : NEG;
            float v2 = (col0 < 5) ? fmaf(c4[u][2], t0.x, t0.y) : NEG;
            float v3 = (col1 < 5) ? fmaf(c4[u][3], t1.x, t1.y) : NEG;

            float mA = fmaxf(v0, v1), mB = fmaxf(v2, v3);
            mA = fmaxf(mA, __shfl_xor_sync(0xffffffffu, mA, 1));
            mB = fmaxf(mB, __shfl_xor_sync(0xffffffffu, mB, 1));
            mA = fmaxf(mA, __shfl_xor_sync(0xffffffffu, mA, 2));
            mB = fmaxf(mB, __shfl_xor_sync(0xffffffffu, mB, 2));
            float e0 = __expf(v0 - mA), e1 = __expf(v1 - mA);
            float e2 = __expf(v2 - mB), e3 = __expf(v3 - mB);
            float sA = e0 + e1, sB = e2 + e3;
            sA += __shfl_xor_sync(0xffffffffu, sA, 1);
            sB += __shfl_xor_sync(0xffffffffu, sB, 1);
            sA += __shfl_xor_sync(0xffffffffu, sA, 2);
            sB += __shfl_xor_sync(0xffffffffu, sB, 2);
            float iA = __fdiv_rn(1.0f, sA), iB = __fdiv_rn(1.0f, sB);

            if (rAg[u] < B) {
                float* q = out + (size_t)rAg[u] * 5;
                if (col0 < 5) q[col0] = e0 * iA;
                if (col1 < 5) q[col1] = e1 * iA;
            }
            if (rBg[u] < B) {
                float* q = out + (size_t)rBg[u] * 5;
                if (col0 < 5) q[col0] = e2 * iB;
                if (col1 < 5) q[col1] = e3 * iB;
            }
        }

        if (lane == 0) p = atomicAdd(&g_ctr, 1u);
        p = __shfl_sync(0xffffffffu, p, 0);
    }
}

// ---------------- launch ----------------
extern "C" void kernel_launch(void* const* d_in, const int* in_sizes, int n_in,
                              void* d_out, int out_size)
{
    const float* x  = (const float*)d_in[0];
    const float* W1 = (const float*)d_in[1];
    const float* b1 = (const float*)d_in[2];
    const float* W2 = (const float*)d_in[3];
    const float* b2 = (const float*)d_in[4];
    const float* W3 = (const float*)d_in[5];
    const float* b3 = (const float*)d_in[6];
    const float* W4 = (const float*)d_in[7];
    const float* b4 = (const float*)d_in[8];

    int B = in_sizes[0] / 16;
    int nTiles = (B + 15) / 16;
    int nPairs = (nTiles + 1) / 2;

    prep_kernel<<<1, 128>>>(W1, b1, W2, b2, W3, b3, W4, b4);

    int grid = 444;                               // 3 CTAs/SM persistent + work stealing
    if (grid > nPairs) grid = nPairs;
    mlp_kernel<<<grid, 128>>>(x, (float*)d_out, B, nPairs);
}